// round 1
// baseline (speedup 1.0000x reference)
#include <cuda_runtime.h>

// Problem constants: volume (2,3,96,96,96) fp32 -> (2,3,192,192,192) fp32
#define NB 6            // batch*channels = 2*3
#define N 96            // input spatial size (all 3 axes)
#define NO 192          // output spatial size
#define SLICE (N * N)   // 9216
#define VOL (N * N * N) // 884736

// Scratch for prefiltered spline coefficients (21.2 MB, static device array)
__device__ float g_coef[NB * VOL];

// ---------------------------------------------------------------------------
// Recursive cubic-spline coefficient prefilter over a 96-element line.
// Matches reference: gain 6 per pass, pole p = sqrt(3)-2, mirror boundary
// causal init (truncated sum; |p|^44 ~ 1e-25), anticausal init c*(p/(p-1)).
// ---------------------------------------------------------------------------
__device__ __forceinline__ void prefilter96(float* b, int stride) {
    const float P = -0.26794919243112270647f;
    const float PDIV = 0.21132486540518711775f; // p/(p-1)

    // causal boundary: c0 = 6*(x0 + p * sum_i p^i x_i)   (p^(2n-*) terms ~ 0)
    float sum = 0.f, pk = 1.f;
#pragma unroll
    for (int i = 0; i < 44; ++i) {
        sum = fmaf(pk, b[i * stride], sum);
        pk *= P;
    }
    float c = 6.0f * fmaf(P, sum, b[0]);
    b[0] = c;

    // causal pass: c[i] = 6*x[i] + p*c[i-1]
#pragma unroll 4
    for (int i = 1; i < N; ++i) {
        c = fmaf(P, c, 6.0f * b[i * stride]);
        b[i * stride] = c;
    }

    // anticausal boundary + pass: y[i] = p*(y[i+1] - c[i])
    float y = c * PDIV;
    b[(N - 1) * stride] = y;
#pragma unroll 4
    for (int i = N - 2; i >= 0; --i) {
        y = P * (y - b[i * stride]);
        b[i * stride] = y;
    }
}

// ---------------------------------------------------------------------------
// Kernel A: prefilter along x then y, one CTA per (b,c,z) slice.
// Slice staged in smem with +1 column pad -> conflict-free in both
// orientations (row access: bank (t*97+i)%32 = (t+i)%32; col access: stride 1).
// ---------------------------------------------------------------------------
__global__ void __launch_bounds__(N) prefilter_xy(const float* __restrict__ in) {
    __shared__ float s[N][N + 1];
    const int slice = blockIdx.x; // (bc, z) flattened: 0..575
    const float* src = in + (long)slice * SLICE;
    float* dst = g_coef + (long)slice * SLICE;
    const int t = threadIdx.x; // 0..95

#pragma unroll 4
    for (int i = 0; i < N; ++i) s[i][t] = src[i * N + t]; // coalesced
    __syncthreads();

    prefilter96(&s[t][0], 1);      // along x (thread t owns row y=t)
    __syncthreads();
    prefilter96(&s[0][t], N + 1);  // along y (thread t owns column x=t)
    __syncthreads();

#pragma unroll 4
    for (int i = 0; i < N; ++i) dst[i * N + t] = s[i][t]; // coalesced
}

// ---------------------------------------------------------------------------
// Kernel B: prefilter along z, one CTA per (b,c,y) slice. In-place on g_coef.
// ---------------------------------------------------------------------------
__global__ void __launch_bounds__(N) prefilter_z() {
    __shared__ float s[N][N + 1];
    const int bc = blockIdx.x / N;
    const int y = blockIdx.x % N;
    float* base = g_coef + (long)bc * VOL + (long)y * N;
    const int t = threadIdx.x; // x index, 0..95

#pragma unroll 4
    for (int z = 0; z < N; ++z) s[z][t] = base[(long)z * SLICE + t]; // coalesced
    __syncthreads();

    prefilter96(&s[0][t], N + 1); // along z
    __syncthreads();

#pragma unroll 4
    for (int z = 0; z < N; ++z) base[(long)z * SLICE + t] = s[z][t];
}

// ---------------------------------------------------------------------------
// Kernel C: fused separable 3D x2 upsample.
// Output tile 8x8x32 from coefficient halo 8x8x20, staged x -> y -> z in smem.
// Even output 2m:   A*c[m-2] + C*c[m-1] + D*c[m] + B*c[m+1]
// Odd  output 2m+1: B*c[m-1] + D*c[m]   + C*c[m+1] + A*c[m+2]
// with {A,B,C,D} = {1,27,121,235}/384, indices clamped to [0,95] (edge pad 2).
// Each thread produces an (even,odd) pair per step: 5 smem reads / 2 outputs.
// ---------------------------------------------------------------------------
#define CZ 4
#define CY 4
#define CX 16
#define IZ (CZ + 4) // 8
#define IY (CY + 4) // 8
#define IX (CX + 4) // 20
#define OZ (2 * CZ) // 8
#define OY (2 * CY) // 8
#define OX (2 * CX) // 32
#define UPS_THREADS 256

__global__ void __launch_bounds__(UPS_THREADS) upsample3d(float* __restrict__ out) {
    __shared__ float s_in[IZ][IY][IX];
    __shared__ float s_x[IZ][IY][OX];
    __shared__ float s_y[IZ][OY][OX];

    const float A = 0.00260416674427688122f; // 1/384
    const float B = 0.0703125f;              // 27/384
    const float C = 0.31510418653488159180f; // 121/384
    const float D = 0.61197918653488159180f; // 235/384

    const int txb = blockIdx.x;            // 0..5
    const int tyb = blockIdx.y;            // 0..23
    const int tzb = blockIdx.z % (N / CZ); // 0..23
    const int bc = blockIdx.z / (N / CZ);  // 0..5
    const int t = threadIdx.x;

    const float* src = g_coef + (long)bc * VOL;
    const int gz0 = tzb * CZ - 2, gy0 = tyb * CY - 2, gx0 = txb * CX - 2;

    // Load coefficient halo with edge clamp
#pragma unroll
    for (int e = t; e < IZ * IY * IX; e += UPS_THREADS) {
        int lx = e % IX;
        int r = e / IX;
        int ly = r % IY;
        int lz = r / IY;
        int gz = min(max(gz0 + lz, 0), N - 1);
        int gy = min(max(gy0 + ly, 0), N - 1);
        int gx = min(max(gx0 + lx, 0), N - 1);
        s_in[lz][ly][lx] = src[((long)gz * N + gy) * N + gx];
    }
    __syncthreads();

    // Stage X: 8*8*16 = 1024 pairs
#pragma unroll
    for (int e = t; e < IZ * IY * CX; e += UPS_THREADS) {
        int h = e % CX;
        int r = e / CX;
        int ly = r % IY;
        int lz = r / IY;
        float v0 = s_in[lz][ly][h + 0];
        float v1 = s_in[lz][ly][h + 1];
        float v2 = s_in[lz][ly][h + 2];
        float v3 = s_in[lz][ly][h + 3];
        float v4 = s_in[lz][ly][h + 4];
        s_x[lz][ly][2 * h + 0] = fmaf(A, v0, fmaf(C, v1, fmaf(D, v2, B * v3)));
        s_x[lz][ly][2 * h + 1] = fmaf(B, v1, fmaf(D, v2, fmaf(C, v3, A * v4)));
    }
    __syncthreads();

    // Stage Y: 8*4*32 = 1024 pairs
#pragma unroll
    for (int e = t; e < IZ * CY * OX; e += UPS_THREADS) {
        int xo = e % OX;
        int r = e / OX;
        int h = r % CY;
        int lz = r / CY;
        float v0 = s_x[lz][h + 0][xo];
        float v1 = s_x[lz][h + 1][xo];
        float v2 = s_x[lz][h + 2][xo];
        float v3 = s_x[lz][h + 3][xo];
        float v4 = s_x[lz][h + 4][xo];
        s_y[lz][2 * h + 0][xo] = fmaf(A, v0, fmaf(C, v1, fmaf(D, v2, B * v3)));
        s_y[lz][2 * h + 1][xo] = fmaf(B, v1, fmaf(D, v2, fmaf(C, v3, A * v4)));
    }
    __syncthreads();

    // Stage Z + coalesced store: 4*8*32 = 1024 pairs
    const long base_out = (((long)bc * NO + (long)tzb * OZ) * NO + (long)tyb * OY) * NO +
                          (long)txb * OX;
#pragma unroll
    for (int e = t; e < CZ * OY * OX; e += UPS_THREADS) {
        int xo = e % OX;
        int r = e / OX;
        int yo = r % OY;
        int h = r / OY;
        float v0 = s_y[h + 0][yo][xo];
        float v1 = s_y[h + 1][yo][xo];
        float v2 = s_y[h + 2][yo][xo];
        float v3 = s_y[h + 3][yo][xo];
        float v4 = s_y[h + 4][yo][xo];
        float o0 = fmaf(A, v0, fmaf(C, v1, fmaf(D, v2, B * v3)));
        float o1 = fmaf(B, v1, fmaf(D, v2, fmaf(C, v3, A * v4)));
        long idx = base_out + (long)(2 * h) * NO * NO + (long)yo * NO + xo;
        out[idx] = o0;
        out[idx + (long)NO * NO] = o1;
    }
}

// ---------------------------------------------------------------------------
extern "C" void kernel_launch(void* const* d_in, const int* in_sizes, int n_in,
                              void* d_out, int out_size) {
    const float* in = (const float*)d_in[0];
    float* out = (float*)d_out;

    prefilter_xy<<<NB * N, N>>>(in);
    prefilter_z<<<NB * N, N>>>();
    upsample3d<<<dim3(N / CX, N / CY, NB * (N / CZ)), UPS_THREADS>>>(out);
}

// round 2
// speedup vs baseline: 1.0319x; 1.0319x over previous
#include <cuda_runtime.h>

// Problem constants: volume (2,3,96,96,96) fp32 -> (2,3,192,192,192) fp32
#define NB 6
#define N 96
#define NO 192
#define SLICE (N * N)
#define VOL (N * N * N)

// Scratch for prefiltered spline coefficients (21.2 MB)
__device__ float g_coef[NB * VOL];

// ---------------------------------------------------------------------------
// FIR formulation of the recursive cubic-spline prefilter (pole p = sqrt3-2).
// Pass A (causal):    c[i] = 6 * sum_{k=0..12} p^k * x_mirror[i-k]
//                     (left extension x[-m] = x[m-1], truncated at |p|^13~3.6e-8)
// Pass B (anticausal):y[i] = sum_{j=0..12} (-p^{j+1}) * c_clamp[i+j]
//                     (right extension c[n+j] = c[n-1], per p/(p-1) init)
// Both passes are embarrassingly parallel; taps are compile-time immediates
// -> FFMA-imm (rt_SMSP=1, 2x throughput vs 3-reg FFMA).
// ---------------------------------------------------------------------------

// dot over w[0..12] where w[k] = x[i-12+k]; taps 6*p^k at k = 12-...
__device__ __forceinline__ float dotA(const float* w) {
    float acc =              8.2182750e-7f * w[0];   // 6*p^12
    acc = fmaf(-3.0674046e-6f, w[1],  acc);          // 6*p^11
    acc = fmaf( 1.1446578e-5f, w[2],  acc);
    acc = fmaf(-4.2719250e-5f, w[3],  acc);
    acc = fmaf( 1.5943030e-4f, w[4],  acc);
    acc = fmaf(-5.9500220e-4f, w[5],  acc);
    acc = fmaf( 2.2205777e-3f, w[6],  acc);
    acc = fmaf(-8.2873086e-3f, w[7],  acc);
    acc = fmaf( 3.0928657e-2f, w[8],  acc);
    acc = fmaf(-1.1542732e-1f, w[9],  acc);
    acc = fmaf( 4.3078062e-1f, w[10], acc);
    acc = fmaf(-1.6076952e0f,  w[11], acc);
    acc = fmaf( 6.0f,          w[12], acc);          // 6*p^0
    return acc;
}

// dot over w[0..12] where w[j] = c[i+j]; taps -p^{j+1}
__device__ __forceinline__ float dotB(const float* w) {
    float acc =              3.6700780e-8f * w[12];  // -p^13
    acc = fmaf(-1.3697125e-7f, w[11], acc);
    acc = fmaf( 5.1123410e-7f, w[10], acc);
    acc = fmaf(-1.9077630e-6f, w[9],  acc);
    acc = fmaf( 7.1198750e-6f, w[8],  acc);
    acc = fmaf(-2.6571710e-5f, w[7],  acc);
    acc = fmaf( 9.9170000e-5f, w[6],  acc);
    acc = fmaf(-3.7009628e-4f, w[5],  acc);
    acc = fmaf( 1.3812181e-3f, w[4],  acc);
    acc = fmaf(-5.1547761e-3f, w[3],  acc);
    acc = fmaf( 1.9237886e-2f, w[2],  acc);
    acc = fmaf(-7.1796770e-2f, w[1],  acc);
    acc = fmaf( 2.6794919e-1f, w[0],  acc);          // -p^1
    return acc;
}

// In-place FIR prefilter of a 96-line in shared memory, compile-time stride.
// Pass A runs groups DESCENDING (group g writes [i0,i0+15]; lower groups only
// read below i0) and pass B ASCENDING (writes [i0,i0+15]; higher groups only
// read above) -> in-place safe, no double buffer, no serial dependence.
template <int S>
__device__ __forceinline__ void fir_line(float* b) {
    // ---- pass A ----
#pragma unroll 1
    for (int g = 5; g >= 1; --g) {
        const int i0 = g * 16;
        float w[28];
#pragma unroll
        for (int k = 0; k < 28; ++k) w[k] = b[(i0 - 12 + k) * S];
        float c[16];
#pragma unroll
        for (int m = 0; m < 16; ++m) c[m] = dotA(w + m);
#pragma unroll
        for (int m = 0; m < 16; ++m) b[(i0 + m) * S] = c[m];
    }
    {   // group 0: mirrored left extension x[-m] = x[m-1]  (idx = j ^ (j>>31))
        float w[28];
#pragma unroll
        for (int k = 0; k < 28; ++k) {
            int j = k - 12;
            int idx = j ^ (j >> 31);
            w[k] = b[idx * S];
        }
        float c[16];
#pragma unroll
        for (int m = 0; m < 16; ++m) c[m] = dotA(w + m);
#pragma unroll
        for (int m = 0; m < 16; ++m) b[m * S] = c[m];
    }
    // ---- pass B ----
#pragma unroll 1
    for (int g = 0; g < 5; ++g) {
        const int i0 = g * 16;
        float w[28];
#pragma unroll
        for (int k = 0; k < 28; ++k) w[k] = b[(i0 + k) * S];
        float y[16];
#pragma unroll
        for (int m = 0; m < 16; ++m) y[m] = dotB(w + m);
#pragma unroll
        for (int m = 0; m < 16; ++m) b[(i0 + m) * S] = y[m];
    }
    {   // group 5: clamped right extension c[>=96] = c[95]
        float w[28];
#pragma unroll
        for (int k = 0; k < 28; ++k) w[k] = b[min(80 + k, 95) * S];
        float y[16];
#pragma unroll
        for (int m = 0; m < 16; ++m) y[m] = dotB(w + m);
#pragma unroll
        for (int m = 0; m < 16; ++m) b[(80 + m) * S] = y[m];
    }
}

// ---------------------------------------------------------------------------
// Kernel A: FIR prefilter along x then y, one CTA per (b,c,z) slice.
// ---------------------------------------------------------------------------
__global__ void __launch_bounds__(N) prefilter_xy(const float* __restrict__ in) {
    __shared__ float s[N][N + 1];
    const int slice = blockIdx.x;
    const float* src = in + (long)slice * SLICE;
    float* dst = g_coef + (long)slice * SLICE;
    const int t = threadIdx.x;

#pragma unroll 4
    for (int i = 0; i < N; ++i) s[i][t] = src[i * N + t];
    __syncthreads();

    fir_line<1>(&s[t][0]);      // along x (thread t owns row y=t)
    __syncthreads();
    fir_line<N + 1>(&s[0][t]);  // along y (thread t owns column x=t)
    __syncthreads();

#pragma unroll 4
    for (int i = 0; i < N; ++i) dst[i * N + t] = s[i][t];
}

// ---------------------------------------------------------------------------
// Kernel B: FIR prefilter along z, one CTA per (b,c,y) slice. In-place.
// ---------------------------------------------------------------------------
__global__ void __launch_bounds__(N) prefilter_z() {
    __shared__ float s[N][N + 1];
    const int bc = blockIdx.x / N;
    const int y = blockIdx.x % N;
    float* base = g_coef + (long)bc * VOL + (long)y * N;
    const int t = threadIdx.x;

#pragma unroll 4
    for (int z = 0; z < N; ++z) s[z][t] = base[(long)z * SLICE + t];
    __syncthreads();

    fir_line<N + 1>(&s[0][t]);  // along z
    __syncthreads();

#pragma unroll 4
    for (int z = 0; z < N; ++z) base[(long)z * SLICE + t] = s[z][t];
}

// ---------------------------------------------------------------------------
// Kernel C: fused separable 3D x2 upsample, register sliding windows.
// Output tile 8x8x32 from coefficient halo 8x8x20.
// Even out 2m:  A*c[m-2] + C*c[m-1] + D*c[m] + B*c[m+1]
// Odd  out 2m+1:B*c[m-1] + D*c[m]   + C*c[m+1] + A*c[m+2]
// {A,B,C,D} = {1,27,121,235}/384, edge clamp 2.
// ---------------------------------------------------------------------------
#define CZ 4
#define CY 4
#define CX 16
#define IZ 8
#define IY 8
#define IX 20
#define SXW 36  // padded s_x row: conflict-free STS.128 in stage X
#define UT 256

#define KA 0.00260416674427688122f
#define KB 0.0703125f
#define KC 0.31510416666666667f
#define KD 0.61197916666666663f

#define UP_EVEN(a, b_, c_, d_) fmaf(KA, (a), fmaf(KC, (b_), fmaf(KD, (c_), KB * (d_))))
#define UP_ODD(a, b_, c_, d_)  fmaf(KB, (a), fmaf(KD, (b_), fmaf(KC, (c_), KA * (d_))))

__global__ void __launch_bounds__(UT) upsample3d(float* __restrict__ out) {
    __shared__ float s_in[IZ][IY][IX];
    __shared__ float s_x[IZ][IY][SXW];
    __shared__ float s_y[IZ][8][32];

    const int txb = blockIdx.x;            // 0..5
    const int tyb = blockIdx.y;            // 0..23
    const int tzb = blockIdx.z % (N / CZ); // 0..23
    const int bc = blockIdx.z / (N / CZ);  // 0..5
    const int t = threadIdx.x;

    const float* src = g_coef + (long)bc * VOL;
    const int gz0 = tzb * CZ - 2, gy0 = tyb * CY - 2, gx0 = txb * CX - 2;

    // Load coefficient halo with edge clamp: 1280 elems / 256 threads
#pragma unroll
    for (int e = t; e < IZ * IY * IX; e += UT) {
        int lx = e % IX;
        int r = e / IX;
        int ly = r % IY;
        int lz = r / IY;
        int gz = min(max(gz0 + lz, 0), N - 1);
        int gy = min(max(gy0 + ly, 0), N - 1);
        int gx = min(max(gx0 + lx, 0), N - 1);
        s_in[lz][ly][lx] = src[((long)gz * N + gy) * N + gx];
    }
    __syncthreads();

    // Stage X: thread (lz,ly,q) handles 4 input steps -> 8 outputs, float4 I/O
    {
        const int q = t & 3, ly = (t >> 2) & 7, lz = t >> 5;
        const float4 p0 = *(const float4*)&s_in[lz][ly][4 * q];
        const float4 p1 = *(const float4*)&s_in[lz][ly][4 * q + 4];
        const float v0 = p0.x, v1 = p0.y, v2 = p0.z, v3 = p0.w;
        const float v4 = p1.x, v5 = p1.y, v6 = p1.z, v7 = p1.w;
        float4 r0, r1;
        r0.x = UP_EVEN(v0, v1, v2, v3);
        r0.y = UP_ODD(v1, v2, v3, v4);
        r0.z = UP_EVEN(v1, v2, v3, v4);
        r0.w = UP_ODD(v2, v3, v4, v5);
        r1.x = UP_EVEN(v2, v3, v4, v5);
        r1.y = UP_ODD(v3, v4, v5, v6);
        r1.z = UP_EVEN(v3, v4, v5, v6);
        r1.w = UP_ODD(v4, v5, v6, v7);
        *(float4*)&s_x[lz][ly][8 * q] = r0;
        *(float4*)&s_x[lz][ly][8 * q + 4] = r1;
    }
    __syncthreads();

    // Stage Y: thread (lz,xo) slides a window over 8 y-inputs -> 8 y-outputs
    {
        const int xo = t & 31, lz = t >> 5;
        const float u0 = s_x[lz][0][xo], u1 = s_x[lz][1][xo];
        const float u2 = s_x[lz][2][xo], u3 = s_x[lz][3][xo];
        const float u4 = s_x[lz][4][xo], u5 = s_x[lz][5][xo];
        const float u6 = s_x[lz][6][xo], u7 = s_x[lz][7][xo];
        s_y[lz][0][xo] = UP_EVEN(u0, u1, u2, u3);
        s_y[lz][1][xo] = UP_ODD(u1, u2, u3, u4);
        s_y[lz][2][xo] = UP_EVEN(u1, u2, u3, u4);
        s_y[lz][3][xo] = UP_ODD(u2, u3, u4, u5);
        s_y[lz][4][xo] = UP_EVEN(u2, u3, u4, u5);
        s_y[lz][5][xo] = UP_ODD(u3, u4, u5, u6);
        s_y[lz][6][xo] = UP_EVEN(u3, u4, u5, u6);
        s_y[lz][7][xo] = UP_ODD(u4, u5, u6, u7);
    }
    __syncthreads();

    // Stage Z: thread (yo,xo) slides over 8 z-inputs -> 8 z-outputs to gmem
    {
        const int xo = t & 31, yo = t >> 5;
        const float u0 = s_y[0][yo][xo], u1 = s_y[1][yo][xo];
        const float u2 = s_y[2][yo][xo], u3 = s_y[3][yo][xo];
        const float u4 = s_y[4][yo][xo], u5 = s_y[5][yo][xo];
        const float u6 = s_y[6][yo][xo], u7 = s_y[7][yo][xo];
        float o[8];
        o[0] = UP_EVEN(u0, u1, u2, u3);
        o[1] = UP_ODD(u1, u2, u3, u4);
        o[2] = UP_EVEN(u1, u2, u3, u4);
        o[3] = UP_ODD(u2, u3, u4, u5);
        o[4] = UP_EVEN(u2, u3, u4, u5);
        o[5] = UP_ODD(u3, u4, u5, u6);
        o[6] = UP_EVEN(u3, u4, u5, u6);
        o[7] = UP_ODD(u4, u5, u6, u7);
        const long base_out = (((long)bc * NO + (long)tzb * (2 * CZ)) * NO +
                               (long)tyb * (2 * CY) + yo) * NO + (long)txb * (2 * CX) + xo;
#pragma unroll
        for (int zo = 0; zo < 8; ++zo)
            out[base_out + (long)zo * NO * NO] = o[zo];
    }
}

// ---------------------------------------------------------------------------
extern "C" void kernel_launch(void* const* d_in, const int* in_sizes, int n_in,
                              void* d_out, int out_size) {
    const float* in = (const float*)d_in[0];
    float* out = (float*)d_out;

    prefilter_xy<<<NB * N, N>>>(in);
    prefilter_z<<<NB * N, N>>>();
    upsample3d<<<dim3(N / CX, N / CY, NB * (N / CZ)), UT>>>(out);
}

// round 3
// speedup vs baseline: 1.1254x; 1.0905x over previous
#include <cuda_runtime.h>

// Problem constants: volume (2,3,96,96,96) fp32 -> (2,3,192,192,192) fp32
#define NB 6
#define N 96
#define NO 192
#define SLICE (N * N)
#define VOL (N * N * N)

// Scratch for prefiltered spline coefficients (21.2 MB)
__device__ float g_coef[NB * VOL];

// ---------------------------------------------------------------------------
// FIR formulation of the recursive cubic-spline prefilter (pole p = sqrt3-2).
// Pass A (causal):    c[i] = 6 * sum_{k=0..12} p^k * x_mirror[i-k]
// Pass B (anticausal):y[i] = sum_{j=0..12} (-p^{j+1}) * c_clamp[i+j]
// Taps are compile-time immediates -> FFMA-imm (rt_SMSP=1).
// Truncation |p|^13 ~ 3.6e-8, far below the 1e-3 tolerance.
// ---------------------------------------------------------------------------
__device__ __forceinline__ float dotA(const float* w) {
    float acc =              8.2182750e-7f * w[0];   // 6*p^12
    acc = fmaf(-3.0674046e-6f, w[1],  acc);
    acc = fmaf( 1.1446578e-5f, w[2],  acc);
    acc = fmaf(-4.2719250e-5f, w[3],  acc);
    acc = fmaf( 1.5943030e-4f, w[4],  acc);
    acc = fmaf(-5.9500220e-4f, w[5],  acc);
    acc = fmaf( 2.2205777e-3f, w[6],  acc);
    acc = fmaf(-8.2873086e-3f, w[7],  acc);
    acc = fmaf( 3.0928657e-2f, w[8],  acc);
    acc = fmaf(-1.1542732e-1f, w[9],  acc);
    acc = fmaf( 4.3078062e-1f, w[10], acc);
    acc = fmaf(-1.6076952e0f,  w[11], acc);
    acc = fmaf( 6.0f,          w[12], acc);          // 6*p^0
    return acc;
}

__device__ __forceinline__ float dotB(const float* w) {
    float acc =              3.6700780e-8f * w[12];  // -p^13
    acc = fmaf(-1.3697125e-7f, w[11], acc);
    acc = fmaf( 5.1123410e-7f, w[10], acc);
    acc = fmaf(-1.9077630e-6f, w[9],  acc);
    acc = fmaf( 7.1198750e-6f, w[8],  acc);
    acc = fmaf(-2.6571710e-5f, w[7],  acc);
    acc = fmaf( 9.9170000e-5f, w[6],  acc);
    acc = fmaf(-3.7009628e-4f, w[5],  acc);
    acc = fmaf( 1.3812181e-3f, w[4],  acc);
    acc = fmaf(-5.1547761e-3f, w[3],  acc);
    acc = fmaf( 1.9237886e-2f, w[2],  acc);
    acc = fmaf(-7.1796770e-2f, w[1],  acc);
    acc = fmaf( 2.6794919e-1f, w[0],  acc);          // -p^1
    return acc;
}

// One group (16 outputs) of pass A for one line at stride S, group index g.
// Read window into regs BEFORE barrier, write in place AFTER -> cross-thread
// in-place safe with 576 parallel group-tasks per slice.
template <int S>
__device__ __forceinline__ void passA_group(float* b, int g) {
    float w[28];
    if (g == 0) {  // mirrored left extension x[-m] = x[m-1]
#pragma unroll
        for (int k = 0; k < 28; ++k) {
            int j = k - 12;
            int idx = j ^ (j >> 31);
            w[k] = b[idx * S];
        }
    } else {
        const int i0 = g * 16;
#pragma unroll
        for (int k = 0; k < 28; ++k) w[k] = b[(i0 - 12 + k) * S];
    }
    float c[16];
#pragma unroll
    for (int m = 0; m < 16; ++m) c[m] = dotA(w + m);
    __syncthreads();
#pragma unroll
    for (int m = 0; m < 16; ++m) b[(g * 16 + m) * S] = c[m];
    __syncthreads();
}

template <int S>
__device__ __forceinline__ void passB_group(float* b, int g) {
    float w[28];
    const int i0 = g * 16;
    if (g == 5) {  // clamped right extension c[>=96] = c[95]
#pragma unroll
        for (int k = 0; k < 28; ++k) w[k] = b[min(80 + k, 95) * S];
    } else {
#pragma unroll
        for (int k = 0; k < 28; ++k) w[k] = b[(i0 + k) * S];
    }
    float y[16];
#pragma unroll
    for (int m = 0; m < 16; ++m) y[m] = dotB(w + m);
    __syncthreads();
#pragma unroll
    for (int m = 0; m < 16; ++m) b[(i0 + m) * S] = y[m];
    __syncthreads();
}

#define PF_THREADS 576  // 96 lines x 6 groups

// ---------------------------------------------------------------------------
// Kernel A: FIR prefilter along x then y, one CTA per (b,c,z) slice.
// Thread (g = t/96, l = t%96): group g of line l. Bank-conflict-free in both
// orientations (row: bank = l + const; column: bank = l).
// ---------------------------------------------------------------------------
__global__ void __launch_bounds__(PF_THREADS, 2) prefilter_xy(const float* __restrict__ in) {
    __shared__ float s[N][N + 1];
    const int slice = blockIdx.x;
    const float* src = in + (long)slice * SLICE;
    float* dst = g_coef + (long)slice * SLICE;
    const int t = threadIdx.x;
    const int g = t / N, l = t % N;

#pragma unroll
    for (int i = 0; i < 16; ++i) {
        int r = g * 16 + i;
        s[r][l] = src[r * N + l];
    }
    __syncthreads();

    passA_group<1>(&s[l][0], g);       // along x (row l)
    passB_group<1>(&s[l][0], g);
    passA_group<N + 1>(&s[0][l], g);   // along y (column l)
    passB_group<N + 1>(&s[0][l], g);

#pragma unroll
    for (int i = 0; i < 16; ++i) {
        int r = g * 16 + i;
        dst[r * N + l] = s[r][l];
    }
}

// ---------------------------------------------------------------------------
// Kernel B: FIR prefilter along z, one CTA per (b,c,y) slice. In-place.
// ---------------------------------------------------------------------------
__global__ void __launch_bounds__(PF_THREADS, 2) prefilter_z() {
    __shared__ float s[N][N + 1];
    const int bc = blockIdx.x / N;
    const int y = blockIdx.x % N;
    float* base = g_coef + (long)bc * VOL + (long)y * N;
    const int t = threadIdx.x;
    const int g = t / N, l = t % N;  // l = x index

#pragma unroll
    for (int i = 0; i < 16; ++i) {
        int z = g * 16 + i;
        s[z][l] = base[(long)z * SLICE + l];
    }
    __syncthreads();

    passA_group<N + 1>(&s[0][l], g);   // along z (column l)
    passB_group<N + 1>(&s[0][l], g);

#pragma unroll
    for (int i = 0; i < 16; ++i) {
        int z = g * 16 + i;
        base[(long)z * SLICE + l] = s[z][l];
    }
}

// ---------------------------------------------------------------------------
// Kernel C: fused separable 3D x2 upsample, register sliding windows.
// Output tile 8x8x32 from coefficient halo 8x8x20.
// Even out 2m:  A*c[m-2] + C*c[m-1] + D*c[m] + B*c[m+1]
// Odd  out 2m+1:B*c[m-1] + D*c[m]   + C*c[m+1] + A*c[m+2]
// {A,B,C,D} = {1,27,121,235}/384, edge clamp 2.
// ---------------------------------------------------------------------------
#define CZ 4
#define CY 4
#define CX 16
#define IZ 8
#define IY 8
#define IX 20
#define SXW 36
#define UT 256

#define KA 0.00260416674427688122f
#define KB 0.0703125f
#define KC 0.31510416666666667f
#define KD 0.61197916666666663f

#define UP_EVEN(a, b_, c_, d_) fmaf(KA, (a), fmaf(KC, (b_), fmaf(KD, (c_), KB * (d_))))
#define UP_ODD(a, b_, c_, d_)  fmaf(KB, (a), fmaf(KD, (b_), fmaf(KC, (c_), KA * (d_))))

__global__ void __launch_bounds__(UT) upsample3d(float* __restrict__ out) {
    __shared__ float s_in[IZ][IY][IX];
    __shared__ float s_x[IZ][IY][SXW];
    __shared__ float s_y[IZ][8][32];

    const int txb = blockIdx.x;
    const int tyb = blockIdx.y;
    const int tzb = blockIdx.z % (N / CZ);
    const int bc = blockIdx.z / (N / CZ);
    const int t = threadIdx.x;

    const float* src = g_coef + (long)bc * VOL;
    const int gz0 = tzb * CZ - 2, gy0 = tyb * CY - 2, gx0 = txb * CX - 2;

#pragma unroll
    for (int e = t; e < IZ * IY * IX; e += UT) {
        int lx = e % IX;
        int r = e / IX;
        int ly = r % IY;
        int lz = r / IY;
        int gz = min(max(gz0 + lz, 0), N - 1);
        int gy = min(max(gy0 + ly, 0), N - 1);
        int gx = min(max(gx0 + lx, 0), N - 1);
        s_in[lz][ly][lx] = src[((long)gz * N + gy) * N + gx];
    }
    __syncthreads();

    // Stage X
    {
        const int q = t & 3, ly = (t >> 2) & 7, lz = t >> 5;
        const float4 p0 = *(const float4*)&s_in[lz][ly][4 * q];
        const float4 p1 = *(const float4*)&s_in[lz][ly][4 * q + 4];
        const float v0 = p0.x, v1 = p0.y, v2 = p0.z, v3 = p0.w;
        const float v4 = p1.x, v5 = p1.y, v6 = p1.z, v7 = p1.w;
        float4 r0, r1;
        r0.x = UP_EVEN(v0, v1, v2, v3);
        r0.y = UP_ODD(v1, v2, v3, v4);
        r0.z = UP_EVEN(v1, v2, v3, v4);
        r0.w = UP_ODD(v2, v3, v4, v5);
        r1.x = UP_EVEN(v2, v3, v4, v5);
        r1.y = UP_ODD(v3, v4, v5, v6);
        r1.z = UP_EVEN(v3, v4, v5, v6);
        r1.w = UP_ODD(v4, v5, v6, v7);
        *(float4*)&s_x[lz][ly][8 * q] = r0;
        *(float4*)&s_x[lz][ly][8 * q + 4] = r1;
    }
    __syncthreads();

    // Stage Y
    {
        const int xo = t & 31, lz = t >> 5;
        const float u0 = s_x[lz][0][xo], u1 = s_x[lz][1][xo];
        const float u2 = s_x[lz][2][xo], u3 = s_x[lz][3][xo];
        const float u4 = s_x[lz][4][xo], u5 = s_x[lz][5][xo];
        const float u6 = s_x[lz][6][xo], u7 = s_x[lz][7][xo];
        s_y[lz][0][xo] = UP_EVEN(u0, u1, u2, u3);
        s_y[lz][1][xo] = UP_ODD(u1, u2, u3, u4);
        s_y[lz][2][xo] = UP_EVEN(u1, u2, u3, u4);
        s_y[lz][3][xo] = UP_ODD(u2, u3, u4, u5);
        s_y[lz][4][xo] = UP_EVEN(u2, u3, u4, u5);
        s_y[lz][5][xo] = UP_ODD(u3, u4, u5, u6);
        s_y[lz][6][xo] = UP_EVEN(u3, u4, u5, u6);
        s_y[lz][7][xo] = UP_ODD(u4, u5, u6, u7);
    }
    __syncthreads();

    // Stage Z + coalesced stores
    {
        const int xo = t & 31, yo = t >> 5;
        const float u0 = s_y[0][yo][xo], u1 = s_y[1][yo][xo];
        const float u2 = s_y[2][yo][xo], u3 = s_y[3][yo][xo];
        const float u4 = s_y[4][yo][xo], u5 = s_y[5][yo][xo];
        const float u6 = s_y[6][yo][xo], u7 = s_y[7][yo][xo];
        float o[8];
        o[0] = UP_EVEN(u0, u1, u2, u3);
        o[1] = UP_ODD(u1, u2, u3, u4);
        o[2] = UP_EVEN(u1, u2, u3, u4);
        o[3] = UP_ODD(u2, u3, u4, u5);
        o[4] = UP_EVEN(u2, u3, u4, u5);
        o[5] = UP_ODD(u3, u4, u5, u6);
        o[6] = UP_EVEN(u3, u4, u5, u6);
        o[7] = UP_ODD(u4, u5, u6, u7);
        const long base_out = (((long)bc * NO + (long)tzb * (2 * CZ)) * NO +
                               (long)tyb * (2 * CY) + yo) * NO + (long)txb * (2 * CX) + xo;
#pragma unroll
        for (int zo = 0; zo < 8; ++zo)
            out[base_out + (long)zo * NO * NO] = o[zo];
    }
}

// ---------------------------------------------------------------------------
extern "C" void kernel_launch(void* const* d_in, const int* in_sizes, int n_in,
                              void* d_out, int out_size) {
    const float* in = (const float*)d_in[0];
    float* out = (float*)d_out;

    prefilter_xy<<<NB * N, PF_THREADS>>>(in);
    prefilter_z<<<NB * N, PF_THREADS>>>();
    upsample3d<<<dim3(N / CX, N / CY, NB * (N / CZ)), UT>>>(out);
}

// round 4
// speedup vs baseline: 1.2862x; 1.1429x over previous
#include <cuda_runtime.h>

// Problem constants: volume (2,3,96,96,96) fp32 -> (2,3,192,192,192) fp32
#define NB 6
#define N 96
#define NO 192
#define SLICE (N * N)
#define VOL (N * N * N)

// Scratch for prefiltered spline coefficients (21.2 MB)
__device__ float g_coef[NB * VOL];

// ---------------------------------------------------------------------------
// Composite cubic B-spline prefilter: causal o anticausal == symmetric FIR
//   h[k] = sqrt(3) * p^|k|,  p = sqrt(3)-2, truncated at |k|<=12 (~2e-7).
// Left mirror boundary is EXACT under composite-with-mirrored-reads (i<=83).
// Right boundary (clamp on causal output c) handled exactly via two-stage.
// All taps are compile-time immediates -> FFMA-imm (rt_SMSP=1).
// ---------------------------------------------------------------------------

// 25-tap symmetric composite: y = sum_{k=0..24} h[|k-12|] * w[k]
__device__ __forceinline__ float dotH(const float* w) {
    float a =                2.3724122e-7f * w[0];
    a = fmaf(-8.8547113e-7f, w[1],  a);
    a = fmaf( 3.3046232e-6f, w[2],  a);
    a = fmaf(-1.2333006e-5f, w[3],  a);
    a = fmaf( 4.6027405e-5f, w[4],  a);
    a = fmaf(-1.7177666e-4f, w[5],  a);
    a = fmaf( 6.4104185e-4f, w[6],  a);
    a = fmaf(-2.3923958e-3f, w[7],  a);
    a = fmaf( 8.9283344e-3f, w[8],  a);
    a = fmaf(-3.3320996e-2f, w[9],  a);
    a = fmaf( 1.2435565e-1f, w[10], a);
    a = fmaf(-4.6410162e-1f, w[11], a);
    a = fmaf( 1.7320508e0f,  w[12], a);
    a = fmaf(-4.6410162e-1f, w[13], a);
    a = fmaf( 1.2435565e-1f, w[14], a);
    a = fmaf(-3.3320996e-2f, w[15], a);
    a = fmaf( 8.9283344e-3f, w[16], a);
    a = fmaf(-2.3923958e-3f, w[17], a);
    a = fmaf( 6.4104185e-4f, w[18], a);
    a = fmaf(-1.7177666e-4f, w[19], a);
    a = fmaf( 4.6027405e-5f, w[20], a);
    a = fmaf(-1.2333006e-5f, w[21], a);
    a = fmaf( 3.3046232e-6f, w[22], a);
    a = fmaf(-8.8547113e-7f, w[23], a);
    a = fmaf( 2.3724122e-7f, w[24], a);
    return a;
}

// causal FIR: c[i] = 6 * sum_{k=0..12} p^k x[i-k]; w[k] = x[i-12+k]
__device__ __forceinline__ float dotA(const float* w) {
    float acc =              8.2182750e-7f * w[0];
    acc = fmaf(-3.0674046e-6f, w[1],  acc);
    acc = fmaf( 1.1446578e-5f, w[2],  acc);
    acc = fmaf(-4.2719250e-5f, w[3],  acc);
    acc = fmaf( 1.5943030e-4f, w[4],  acc);
    acc = fmaf(-5.9500220e-4f, w[5],  acc);
    acc = fmaf( 2.2205777e-3f, w[6],  acc);
    acc = fmaf(-8.2873086e-3f, w[7],  acc);
    acc = fmaf( 3.0928657e-2f, w[8],  acc);
    acc = fmaf(-1.1542732e-1f, w[9],  acc);
    acc = fmaf( 4.3078062e-1f, w[10], acc);
    acc = fmaf(-1.6076952e0f,  w[11], acc);
    acc = fmaf( 6.0f,          w[12], acc);
    return acc;
}

// anticausal FIR: y[i] = sum_{j=0..12} (-p^{j+1}) c[i+j]; w[j] = c[i+j]
__device__ __forceinline__ float dotB(const float* w) {
    float acc =              3.6700780e-8f * w[12];
    acc = fmaf(-1.3697125e-7f, w[11], acc);
    acc = fmaf( 5.1123410e-7f, w[10], acc);
    acc = fmaf(-1.9077630e-6f, w[9],  acc);
    acc = fmaf( 7.1198750e-6f, w[8],  acc);
    acc = fmaf(-2.6571710e-5f, w[7],  acc);
    acc = fmaf( 9.9170000e-5f, w[6],  acc);
    acc = fmaf(-3.7009628e-4f, w[5],  acc);
    acc = fmaf( 1.3812181e-3f, w[4],  acc);
    acc = fmaf(-5.1547761e-3f, w[3],  acc);
    acc = fmaf( 1.9237886e-2f, w[2],  acc);
    acc = fmaf(-7.1796770e-2f, w[1],  acc);
    acc = fmaf( 2.6794919e-1f, w[0],  acc);
    return acc;
}

// One full prefilter phase (both IIR passes fused) over a 96-line, stride S.
// Thread owns group g (16 outputs). Reads window into registers BEFORE the
// barrier, writes in place AFTER -> cross-thread in-place safe.
template <int S>
__device__ __forceinline__ void phase(float* b, int g) {
    float yv[16];
    if (g == 0) {  // left edge: composite on mirror-extended reads (exact)
        float w[40];
#pragma unroll
        for (int k = 0; k < 40; ++k) {
            int j = k - 12;
            int idx = j ^ (j >> 31);  // mirror x[-m] = x[m-1]
            w[k] = b[idx * S];
        }
#pragma unroll
        for (int m = 0; m < 16; ++m) yv[m] = dotH(w + m);
    } else if (g < 5) {  // interior
        float w[40];
#pragma unroll
        for (int k = 0; k < 40; ++k) w[k] = b[(g * 16 - 12 + k) * S];
#pragma unroll
        for (int m = 0; m < 16; ++m) yv[m] = dotH(w + m);
    } else {  // right edge: outputs 80..83 composite; 84..95 exact two-stage
        float xw[28];  // x[68..95]
#pragma unroll
        for (int k = 0; k < 28; ++k) xw[k] = b[(68 + k) * S];
#pragma unroll
        for (int m = 0; m < 4; ++m) yv[m] = dotH(xw + m);
        float ce[24];  // c[84..95] then clamp-extension c[95]
#pragma unroll
        for (int j = 0; j < 12; ++j) ce[j] = dotA(xw + 4 + j);
#pragma unroll
        for (int j = 12; j < 24; ++j) ce[j] = ce[11];
#pragma unroll
        for (int m = 0; m < 12; ++m) yv[4 + m] = dotB(ce + m);
    }
    __syncthreads();
#pragma unroll
    for (int m = 0; m < 16; ++m) b[(g * 16 + m) * S] = yv[m];
    __syncthreads();
}

#define PF_THREADS 576  // 96 lines x 6 groups

// ---------------------------------------------------------------------------
// Kernel A: prefilter along x then y, one CTA per (b,c,z) slice.
// ---------------------------------------------------------------------------
__global__ void __launch_bounds__(PF_THREADS, 2) prefilter_xy(const float* __restrict__ in) {
    __shared__ float s[N][N + 1];
    const int slice = blockIdx.x;
    const float* src = in + (long)slice * SLICE;
    float* dst = g_coef + (long)slice * SLICE;
    const int t = threadIdx.x;
    const int g = t / N, l = t % N;

#pragma unroll
    for (int i = 0; i < 16; ++i) {
        int r = g * 16 + i;
        s[r][l] = src[r * N + l];
    }
    __syncthreads();

    phase<1>(&s[l][0], g);       // along x (row l)
    phase<N + 1>(&s[0][l], g);   // along y (column l)

#pragma unroll
    for (int i = 0; i < 16; ++i) {
        int r = g * 16 + i;
        dst[r * N + l] = s[r][l];
    }
}

// ---------------------------------------------------------------------------
// Kernel B: prefilter along z, one CTA per (b,c,y) slice. In-place.
// ---------------------------------------------------------------------------
__global__ void __launch_bounds__(PF_THREADS, 2) prefilter_z() {
    __shared__ float s[N][N + 1];
    const int bc = blockIdx.x / N;
    const int y = blockIdx.x % N;
    float* base = g_coef + (long)bc * VOL + (long)y * N;
    const int t = threadIdx.x;
    const int g = t / N, l = t % N;  // l = x index

#pragma unroll
    for (int i = 0; i < 16; ++i) {
        int z = g * 16 + i;
        s[z][l] = base[(long)z * SLICE + l];
    }
    __syncthreads();

    phase<N + 1>(&s[0][l], g);   // along z (column l)

#pragma unroll
    for (int i = 0; i < 16; ++i) {
        int z = g * 16 + i;
        base[(long)z * SLICE + l] = s[z][l];
    }
}

// ---------------------------------------------------------------------------
// Kernel C: fused separable 3D x2 upsample.
// Coeff tile 4x8x16 (+2 halo each side) -> output tile 8x16x32.
// Even out 2m:  A*c[m-2] + C*c[m-1] + D*c[m] + B*c[m+1]
// Odd  out 2m+1:B*c[m-1] + D*c[m]   + C*c[m+1] + A*c[m+2]
// {A,B,C,D} = {1,27,121,235}/384, edge clamp 2. Streaming stores (__stcs)
// keep g_coef resident in L2 (output is write-once, 170 MB).
// ---------------------------------------------------------------------------
#define CZ 4
#define CY 8
#define CX 16
#define IZ 8
#define IY 12
#define IX 20
#define SXW 36
#define UT 256

#define KA 0.00260416674427688122f
#define KB 0.0703125f
#define KC 0.31510416666666667f
#define KD 0.61197916666666663f

#define UP_EVEN(a, b_, c_, d_) fmaf(KA, (a), fmaf(KC, (b_), fmaf(KD, (c_), KB * (d_))))
#define UP_ODD(a, b_, c_, d_)  fmaf(KB, (a), fmaf(KD, (b_), fmaf(KC, (c_), KA * (d_))))

__global__ void __launch_bounds__(UT) upsample3d(float* __restrict__ out) {
    __shared__ float s_in[IZ][IY][IX];   // 1920 floats
    __shared__ float s_x[IZ][IY][SXW];   // 3456 floats (pad 36: conflict-free STS.128)
    __shared__ float s_y[IZ][2 * CY][2 * CX]; // 4096 floats

    const int txb = blockIdx.x;            // 0..5
    const int tyb = blockIdx.y;            // 0..11
    const int tzb = blockIdx.z % (N / CZ); // 0..23
    const int bc = blockIdx.z / (N / CZ);  // 0..5
    const int t = threadIdx.x;

    const float* src = g_coef + (long)bc * VOL;
    const int gz0 = tzb * CZ - 2, gy0 = tyb * CY - 2, gx0 = txb * CX - 2;

    // Halo load with edge clamp: 1920 elems / 256 threads
#pragma unroll
    for (int e = t; e < IZ * IY * IX; e += UT) {
        int lx = e % IX;
        int r = e / IX;
        int ly = r % IY;
        int lz = r / IY;
        int gz = min(max(gz0 + lz, 0), N - 1);
        int gy = min(max(gy0 + ly, 0), N - 1);
        int gx = min(max(gx0 + lx, 0), N - 1);
        s_in[lz][ly][lx] = src[((long)gz * N + gy) * N + gx];
    }
    __syncthreads();

    // Stage X: 96 lines x 4 quads = 384 tasks; each task 8 inputs -> 8 outputs
#pragma unroll
    for (int e = t; e < IZ * IY * 4; e += UT) {
        int q = e & 3;
        int r = e >> 2;
        int ly = r % IY;
        int lz = r / IY;
        const float4 p0 = *(const float4*)&s_in[lz][ly][4 * q];
        const float4 p1 = *(const float4*)&s_in[lz][ly][4 * q + 4];
        const float v0 = p0.x, v1 = p0.y, v2 = p0.z, v3 = p0.w;
        const float v4 = p1.x, v5 = p1.y, v6 = p1.z, v7 = p1.w;
        float4 r0, r1;
        r0.x = UP_EVEN(v0, v1, v2, v3);
        r0.y = UP_ODD(v1, v2, v3, v4);
        r0.z = UP_EVEN(v1, v2, v3, v4);
        r0.w = UP_ODD(v2, v3, v4, v5);
        r1.x = UP_EVEN(v2, v3, v4, v5);
        r1.y = UP_ODD(v3, v4, v5, v6);
        r1.z = UP_EVEN(v3, v4, v5, v6);
        r1.w = UP_ODD(v4, v5, v6, v7);
        *(float4*)&s_x[lz][ly][8 * q] = r0;
        *(float4*)&s_x[lz][ly][8 * q + 4] = r1;
    }
    __syncthreads();

    // Stage Y: 32 xo x 8 lz = 256 tasks; window of 12 -> 16 y-outputs
    {
        const int xo = t & 31, lz = t >> 5;
        float u[IY];
#pragma unroll
        for (int h = 0; h < IY; ++h) u[h] = s_x[lz][h][xo];
#pragma unroll
        for (int h = 0; h < CY; ++h) {
            s_y[lz][2 * h + 0][xo] = UP_EVEN(u[h], u[h + 1], u[h + 2], u[h + 3]);
            s_y[lz][2 * h + 1][xo] = UP_ODD(u[h + 1], u[h + 2], u[h + 3], u[h + 4]);
        }
    }
    __syncthreads();

    // Stage Z: 32 xo x 16 yo = 512 tasks; window of 8 -> 8 z-outputs to gmem
#pragma unroll
    for (int e = t; e < 512; e += UT) {
        const int xo = e & 31, yo = e >> 5;
        float u[IZ];
#pragma unroll
        for (int h = 0; h < IZ; ++h) u[h] = s_y[h][yo][xo];
        const long base_out = (((long)bc * NO + (long)tzb * (2 * CZ)) * NO +
                               (long)tyb * (2 * CY) + yo) * NO + (long)txb * (2 * CX) + xo;
#pragma unroll
        for (int h = 0; h < CZ; ++h) {
            float o0 = UP_EVEN(u[h], u[h + 1], u[h + 2], u[h + 3]);
            float o1 = UP_ODD(u[h + 1], u[h + 2], u[h + 3], u[h + 4]);
            __stcs(&out[base_out + (long)(2 * h) * NO * NO], o0);
            __stcs(&out[base_out + (long)(2 * h + 1) * NO * NO], o1);
        }
    }
}

// ---------------------------------------------------------------------------
extern "C" void kernel_launch(void* const* d_in, const int* in_sizes, int n_in,
                              void* d_out, int out_size) {
    const float* in = (const float*)d_in[0];
    float* out = (float*)d_out;

    prefilter_xy<<<NB * N, PF_THREADS>>>(in);
    prefilter_z<<<NB * N, PF_THREADS>>>();
    upsample3d<<<dim3(N / CX, N / CY, NB * (N / CZ)), UT>>>(out);
}

// round 5
// speedup vs baseline: 1.5818x; 1.2298x over previous
#include <cuda_runtime.h>

// Problem constants: volume (2,3,96,96,96) fp32 -> (2,3,192,192,192) fp32
#define NB 6
#define N 96
#define NO 192
#define SLICE (N * N)
#define VOL (N * N * N)

// Scratch for prefiltered spline coefficients (21.2 MB)
__device__ float g_coef[NB * VOL];

// ---------------------------------------------------------------------------
// Composite cubic B-spline prefilter: causal o anticausal == symmetric FIR
//   h[k] = sqrt(3) * p^|k|,  p = sqrt(3)-2, truncated at |k|<=12 (~2e-7).
// Left mirror boundary exact via mirrored reads; right boundary exact via
// two-stage (causal FIR -> clamp -> anticausal FIR). Taps are immediates.
// ---------------------------------------------------------------------------
__device__ __forceinline__ float dotH(const float* w) {
    float a =                2.3724122e-7f * w[0];
    a = fmaf(-8.8547113e-7f, w[1],  a);
    a = fmaf( 3.3046232e-6f, w[2],  a);
    a = fmaf(-1.2333006e-5f, w[3],  a);
    a = fmaf( 4.6027405e-5f, w[4],  a);
    a = fmaf(-1.7177666e-4f, w[5],  a);
    a = fmaf( 6.4104185e-4f, w[6],  a);
    a = fmaf(-2.3923958e-3f, w[7],  a);
    a = fmaf( 8.9283344e-3f, w[8],  a);
    a = fmaf(-3.3320996e-2f, w[9],  a);
    a = fmaf( 1.2435565e-1f, w[10], a);
    a = fmaf(-4.6410162e-1f, w[11], a);
    a = fmaf( 1.7320508e0f,  w[12], a);
    a = fmaf(-4.6410162e-1f, w[13], a);
    a = fmaf( 1.2435565e-1f, w[14], a);
    a = fmaf(-3.3320996e-2f, w[15], a);
    a = fmaf( 8.9283344e-3f, w[16], a);
    a = fmaf(-2.3923958e-3f, w[17], a);
    a = fmaf( 6.4104185e-4f, w[18], a);
    a = fmaf(-1.7177666e-4f, w[19], a);
    a = fmaf( 4.6027405e-5f, w[20], a);
    a = fmaf(-1.2333006e-5f, w[21], a);
    a = fmaf( 3.3046232e-6f, w[22], a);
    a = fmaf(-8.8547113e-7f, w[23], a);
    a = fmaf( 2.3724122e-7f, w[24], a);
    return a;
}

__device__ __forceinline__ float dotA(const float* w) {
    float acc =              8.2182750e-7f * w[0];
    acc = fmaf(-3.0674046e-6f, w[1],  acc);
    acc = fmaf( 1.1446578e-5f, w[2],  acc);
    acc = fmaf(-4.2719250e-5f, w[3],  acc);
    acc = fmaf( 1.5943030e-4f, w[4],  acc);
    acc = fmaf(-5.9500220e-4f, w[5],  acc);
    acc = fmaf( 2.2205777e-3f, w[6],  acc);
    acc = fmaf(-8.2873086e-3f, w[7],  acc);
    acc = fmaf( 3.0928657e-2f, w[8],  acc);
    acc = fmaf(-1.1542732e-1f, w[9],  acc);
    acc = fmaf( 4.3078062e-1f, w[10], acc);
    acc = fmaf(-1.6076952e0f,  w[11], acc);
    acc = fmaf( 6.0f,          w[12], acc);
    return acc;
}

__device__ __forceinline__ float dotB(const float* w) {
    float acc =              3.6700780e-8f * w[12];
    acc = fmaf(-1.3697125e-7f, w[11], acc);
    acc = fmaf( 5.1123410e-7f, w[10], acc);
    acc = fmaf(-1.9077630e-6f, w[9],  acc);
    acc = fmaf( 7.1198750e-6f, w[8],  acc);
    acc = fmaf(-2.6571710e-5f, w[7],  acc);
    acc = fmaf( 9.9170000e-5f, w[6],  acc);
    acc = fmaf(-3.7009628e-4f, w[5],  acc);
    acc = fmaf( 1.3812181e-3f, w[4],  acc);
    acc = fmaf(-5.1547761e-3f, w[3],  acc);
    acc = fmaf( 1.9237886e-2f, w[2],  acc);
    acc = fmaf(-7.1796770e-2f, w[1],  acc);
    acc = fmaf( 2.6794919e-1f, w[0],  acc);
    return acc;
}

// One prefilter phase for group g of a 96-line: reads bsrc, writes bdst
// (ping-pong -> NO internal barriers; caller syncs between phases).
template <int S>
__device__ __forceinline__ void phaseP(const float* bsrc, float* bdst, int g) {
    float yv[16];
    if (g == 0) {  // left edge: composite on mirror-extended reads (exact)
        float w[40];
#pragma unroll
        for (int k = 0; k < 40; ++k) {
            int j = k - 12;
            int idx = j ^ (j >> 31);  // mirror x[-m] = x[m-1]
            w[k] = bsrc[idx * S];
        }
#pragma unroll
        for (int m = 0; m < 16; ++m) yv[m] = dotH(w + m);
    } else if (g < 5) {  // interior
        float w[40];
#pragma unroll
        for (int k = 0; k < 40; ++k) w[k] = bsrc[(g * 16 - 12 + k) * S];
#pragma unroll
        for (int m = 0; m < 16; ++m) yv[m] = dotH(w + m);
    } else {  // right edge: 80..83 composite; 84..95 exact two-stage
        float xw[28];
#pragma unroll
        for (int k = 0; k < 28; ++k) xw[k] = bsrc[(68 + k) * S];
#pragma unroll
        for (int m = 0; m < 4; ++m) yv[m] = dotH(xw + m);
        float ce[24];
#pragma unroll
        for (int j = 0; j < 12; ++j) ce[j] = dotA(xw + 4 + j);
#pragma unroll
        for (int j = 12; j < 24; ++j) ce[j] = ce[11];
#pragma unroll
        for (int m = 0; m < 12; ++m) yv[4 + m] = dotB(ce + m);
    }
#pragma unroll
    for (int m = 0; m < 16; ++m) bdst[(g * 16 + m) * S] = yv[m];
}

#define PF_THREADS 576  // 96 lines x 6 groups
#define PF_SMEM (2 * N * (N + 1) * 4)  // ping-pong pair, bytes

// ---------------------------------------------------------------------------
// Kernel A: prefilter x then y, one CTA per (b,c,z) slice. Dynamic smem
// ping-pong: only 2 barriers total.
// ---------------------------------------------------------------------------
__global__ void __launch_bounds__(PF_THREADS, 2) prefilter_xy(const float* __restrict__ in) {
    extern __shared__ float sm[];
    float* s0 = sm;
    float* s1 = sm + N * (N + 1);
    const int slice = blockIdx.x;
    const float* src = in + (long)slice * SLICE;
    float* dst = g_coef + (long)slice * SLICE;
    const int t = threadIdx.x;
    const int g = t / N, l = t % N;

#pragma unroll
    for (int i = 0; i < 16; ++i) {
        int r = g * 16 + i;
        s0[r * (N + 1) + l] = src[r * N + l];
    }
    __syncthreads();

    phaseP<1>(&s0[l * (N + 1)], &s1[l * (N + 1)], g);  // x: row l
    __syncthreads();
    phaseP<N + 1>(&s1[l], &s0[l], g);                  // y: column l

    // store reads only elements this thread just wrote -> no barrier
#pragma unroll
    for (int i = 0; i < 16; ++i) {
        int r = g * 16 + i;
        dst[r * N + l] = s0[r * (N + 1) + l];
    }
}

// ---------------------------------------------------------------------------
// Kernel B: prefilter along z, one CTA per (b,c,y) slice. 1 barrier.
// ---------------------------------------------------------------------------
__global__ void __launch_bounds__(PF_THREADS, 2) prefilter_z() {
    extern __shared__ float sm[];
    float* s0 = sm;
    float* s1 = sm + N * (N + 1);
    const int bc = blockIdx.x / N;
    const int y = blockIdx.x % N;
    float* base = g_coef + (long)bc * VOL + (long)y * N;
    const int t = threadIdx.x;
    const int g = t / N, l = t % N;  // l = x index

#pragma unroll
    for (int i = 0; i < 16; ++i) {
        int z = g * 16 + i;
        s0[z * (N + 1) + l] = base[(long)z * SLICE + l];
    }
    __syncthreads();

    phaseP<N + 1>(&s0[l], &s1[l], g);  // z: column l

#pragma unroll
    for (int i = 0; i < 16; ++i) {
        int z = g * 16 + i;
        base[(long)z * SLICE + l] = s1[z * (N + 1) + l];
    }
}

// ---------------------------------------------------------------------------
// Kernel C: fused separable 3D x2 upsample.
// Coeff tile 8x8x16 (+2 halo each side) -> output tile 16x16x32.
// Even out 2m:  A*c[m-2] + C*c[m-1] + D*c[m] + B*c[m+1]
// Odd  out 2m+1:B*c[m-1] + D*c[m]   + C*c[m+1] + A*c[m+2]
// s_y aliases dead s_in; STG.128 streaming stores.
// ---------------------------------------------------------------------------
#define CZ 8
#define CY 8
#define CX 16
#define IZ 12
#define IY 12
#define IX 20
#define SXW 36
#define UT 256

#define KA 0.00260416674427688122f
#define KB 0.0703125f
#define KC 0.31510416666666667f
#define KD 0.61197916666666663f

#define UP_EVEN(a, b_, c_, d_) fmaf(KA, (a), fmaf(KC, (b_), fmaf(KD, (c_), KB * (d_))))
#define UP_ODD(a, b_, c_, d_)  fmaf(KB, (a), fmaf(KD, (b_), fmaf(KC, (c_), KA * (d_))))

__device__ __forceinline__ float4 up_even4(float4 a, float4 b, float4 c, float4 d) {
    float4 r;
    r.x = UP_EVEN(a.x, b.x, c.x, d.x);
    r.y = UP_EVEN(a.y, b.y, c.y, d.y);
    r.z = UP_EVEN(a.z, b.z, c.z, d.z);
    r.w = UP_EVEN(a.w, b.w, c.w, d.w);
    return r;
}
__device__ __forceinline__ float4 up_odd4(float4 a, float4 b, float4 c, float4 d) {
    float4 r;
    r.x = UP_ODD(a.x, b.x, c.x, d.x);
    r.y = UP_ODD(a.y, b.y, c.y, d.y);
    r.z = UP_ODD(a.z, b.z, c.z, d.z);
    r.w = UP_ODD(a.w, b.w, c.w, d.w);
    return r;
}

// smem: s_x [IZ][IY][SXW] = 5184 floats, then region R = 6144 floats used as
// s_in [IZ][IY][IX] (2880, dead after stage X) then s_y [IZ][16][32].
__global__ void __launch_bounds__(UT) upsample3d(float* __restrict__ out) {
    __shared__ float sm[5184 + 6144];  // 45.3 KB
    float* s_x = sm;
    float* s_in = sm + 5184;
    float* s_y = sm + 5184;

    const int txb = blockIdx.x;            // 0..5
    const int tyb = blockIdx.y;            // 0..11
    const int tzb = blockIdx.z % (N / CZ); // 0..11
    const int bc = blockIdx.z / (N / CZ);  // 0..5
    const int t = threadIdx.x;

    const float* src = g_coef + (long)bc * VOL;
    const int gz0 = tzb * CZ - 2, gy0 = tyb * CY - 2, gx0 = txb * CX - 2;

    // Halo load with edge clamp: 2880 elems
#pragma unroll
    for (int e = t; e < IZ * IY * IX; e += UT) {
        int lx = e % IX;
        int r = e / IX;
        int ly = r % IY;
        int lz = r / IY;
        int gz = min(max(gz0 + lz, 0), N - 1);
        int gy = min(max(gy0 + ly, 0), N - 1);
        int gx = min(max(gx0 + lx, 0), N - 1);
        s_in[(lz * IY + ly) * IX + lx] = src[((long)gz * N + gy) * N + gx];
    }
    __syncthreads();

    // Stage X: 144 lines x 4 quads = 576 tasks; 8 in -> 8 out each (float4 IO)
#pragma unroll
    for (int e = t; e < IZ * IY * 4; e += UT) {
        int q = e & 3;
        int line = e >> 2;  // lz*IY + ly
        const float* row = &s_in[line * IX + 4 * q];
        const float4 p0 = *(const float4*)row;
        const float4 p1 = *(const float4*)(row + 4);
        const float v0 = p0.x, v1 = p0.y, v2 = p0.z, v3 = p0.w;
        const float v4 = p1.x, v5 = p1.y, v6 = p1.z, v7 = p1.w;
        float4 r0, r1;
        r0.x = UP_EVEN(v0, v1, v2, v3);
        r0.y = UP_ODD(v1, v2, v3, v4);
        r0.z = UP_EVEN(v1, v2, v3, v4);
        r0.w = UP_ODD(v2, v3, v4, v5);
        r1.x = UP_EVEN(v2, v3, v4, v5);
        r1.y = UP_ODD(v3, v4, v5, v6);
        r1.z = UP_EVEN(v3, v4, v5, v6);
        r1.w = UP_ODD(v4, v5, v6, v7);
        *(float4*)&s_x[line * SXW + 8 * q] = r0;
        *(float4*)&s_x[line * SXW + 8 * q + 4] = r1;
    }
    __syncthreads();  // also: s_in reads complete before s_y overwrites region

    // Stage Y: (lz 0..11, xo 0..31) = 384 tasks; window 12 -> 16 y-outputs
#pragma unroll
    for (int e = t; e < IZ * 32; e += UT) {
        const int xo = e & 31, lz = e >> 5;
        float u[IY];
#pragma unroll
        for (int h = 0; h < IY; ++h) u[h] = s_x[(lz * IY + h) * SXW + xo];
#pragma unroll
        for (int h = 0; h < CY; ++h) {
            s_y[(lz * 16 + 2 * h) * 32 + xo] = UP_EVEN(u[h], u[h + 1], u[h + 2], u[h + 3]);
            s_y[(lz * 16 + 2 * h + 1) * 32 + xo] = UP_ODD(u[h + 1], u[h + 2], u[h + 3], u[h + 4]);
        }
    }
    __syncthreads();

    // Stage Z: thread (zq, yo, xq) -> 8 z-outputs x float4; STG.128 streaming
    {
        const int xq = t & 7, yo = (t >> 3) & 15, zq = t >> 7;  // zq 0..1
        float4 u[8];
#pragma unroll
        for (int i = 0; i < 8; ++i)
            u[i] = *(const float4*)&s_y[((4 * zq + i) * 16 + yo) * 32 + 4 * xq];
        const long base_out = (((long)bc * NO + (long)tzb * (2 * CZ)) * NO +
                               (long)tyb * (2 * CY) + yo) * NO + (long)txb * (2 * CX) + 4 * xq;
#pragma unroll
        for (int hh = 0; hh < 4; ++hh) {
            float4 o0 = up_even4(u[hh], u[hh + 1], u[hh + 2], u[hh + 3]);
            float4 o1 = up_odd4(u[hh + 1], u[hh + 2], u[hh + 3], u[hh + 4]);
            const long zo = 2 * (4 * zq + hh);
            __stcs((float4*)&out[base_out + zo * NO * NO], o0);
            __stcs((float4*)&out[base_out + (zo + 1) * NO * NO], o1);
        }
    }
}

// ---------------------------------------------------------------------------
extern "C" void kernel_launch(void* const* d_in, const int* in_sizes, int n_in,
                              void* d_out, int out_size) {
    const float* in = (const float*)d_in[0];
    float* out = (float*)d_out;

    cudaFuncSetAttribute(prefilter_xy, cudaFuncAttributeMaxDynamicSharedMemorySize, PF_SMEM);
    cudaFuncSetAttribute(prefilter_z, cudaFuncAttributeMaxDynamicSharedMemorySize, PF_SMEM);

    prefilter_xy<<<NB * N, PF_THREADS, PF_SMEM>>>(in);
    prefilter_z<<<NB * N, PF_THREADS, PF_SMEM>>>();
    upsample3d<<<dim3(N / CX, N / CY, NB * (N / CZ)), UT>>>(out);
}